// round 16
// baseline (speedup 1.0000x reference)
#include <cuda_runtime.h>
#include <cuda_bf16.h>
#include <cuda_fp16.h>
#include <mma.h>
#include <math.h>

using namespace nvcuda;

#define NN 100000
#define EE 1250000
#define ET (NN + EE)          // edges + self loops
#define CC 10
#define NB 391                // ceil(NN/256)

// -------- scratch (no allocations allowed) --------
__device__ __half g_lin[(NN + 128) * 64];  // fp16 features (+pad rows for unguarded wmma store)
__device__ __half g_act[NN * 64];    // fp16 aggregated activations
__device__ int   g_deg[NN];          // starts zero (BSS); re-zeroed by k_rp each launch
__device__ int   g_rowptr[NN];
__device__ int   g_len[NN];
__device__ int   g_cursor[NN];
__device__ int   g_csr[ET];
__device__ float g_wcsr[ET];         // per-slot GCN norm (written in csr_fill)
__device__ float g_ev[ET];           // per-slot GAT exp(logit)
__device__ float g_dinv[NN];
__device__ float g_as[NN];
__device__ float g_ad[NN];
__device__ float g_emb[64];
__device__ int   g_ctr[4];           // [0]=rp base, [1]=rp ticket, [2]=heads ticket

// ======== CSR build ========
__global__ void k_deg_count(const int* __restrict__ dst, int* deg) {
    int t0 = blockIdx.x * 1024 + threadIdx.x;
#pragma unroll
    for (int j = 0; j < 4; j++) {
        int i = t0 + j * 256;
        if (i < EE) atomicAdd(&deg[dst[i]], 1);
    }
}
__global__ void k_rp(int* __restrict__ deg, int* __restrict__ rp, int* __restrict__ cur,
                     int* __restrict__ len, float* __restrict__ dinv,
                     float* __restrict__ emb, int* __restrict__ ctr) {
    __shared__ int s[256];
    __shared__ int base;
    int t = threadIdx.x;
    int i = blockIdx.x * 256 + t;
    int v = (i < NN) ? (deg[i] + 1) : 0;       // +1 self loop
    s[t] = v;
    __syncthreads();
    for (int off = 1; off < 256; off <<= 1) {
        int u = (t >= off) ? s[t - off] : 0;
        __syncthreads();
        s[t] += u;
        __syncthreads();
    }
    if (t == 255) base = atomicAdd(&ctr[0], s[255]);
    __syncthreads();
    if (i < NN) {
        int ex = base + s[t] - v;
        rp[i] = ex;
        cur[i] = ex;
        len[i] = v;
        dinv[i] = rsqrtf((float)v);
        deg[i] = 0;                            // ready for next replay
    }
    if (blockIdx.x == 0 && t < 64) emb[t] = 0.f;
    __threadfence();
    if (t == 0) {
        int done = atomicAdd(&ctr[1], 1);
        if (done == gridDim.x - 1) { ctr[0] = 0; ctr[1] = 0; }
    }
}
__global__ void k_csr_fill(const int* __restrict__ src, const int* __restrict__ dst,
                           int* __restrict__ cur, int* __restrict__ csr,
                           const float* __restrict__ dinv, float* __restrict__ wcsr) {
    int t0 = blockIdx.x * 1024 + threadIdx.x;
#pragma unroll
    for (int j = 0; j < 4; j++) {
        int i = t0 + j * 256;
        if (i < ET) {
            int s, d;
            if (i < EE) { s = src[i]; d = dst[i]; } else { s = d = i - EE; }
            int pos = atomicAdd(&cur[d], 1);
            csr[pos] = s;
            wcsr[pos] = dinv[s] * dinv[d];
        }
    }
}

// ======== tensor-core GEMM: C_h[M,64] = A[M,K] @ W[K,64], fp16 in / fp32 accum ========
__device__ __forceinline__ uint2 cvt4(float4 v) {
    __half2 h0 = __float22half2_rn(make_float2(v.x, v.y));
    __half2 h1 = __float22half2_rn(make_float2(v.z, v.w));
    uint2 r;
    r.x = *(unsigned*)&h0;
    r.y = *(unsigned*)&h1;
    return r;
}

// ALPHA=false: direct half-fragment store (no staging). ALPHA=true: Os staging + fused as/ad.
// AHALF: A already fp16.
template <int K, bool ALPHA, bool AHALF>
__global__ void k_gemm_t(const void* __restrict__ Avoid, const float* __restrict__ W,
                         __half* __restrict__ C,
                         const float* __restrict__ avs, const float* __restrict__ avd,
                         float* __restrict__ as_out, float* __restrict__ ad_out, int M) {
    extern __shared__ char smx[];
    const int AS = K + 8;                       // halves per As row
    __half* As = (__half*)smx;                  // 128*AS halves
    __half* Ws = As + 128 * AS;                 // K*72 halves
    float*  Os = (float*)smx;                   // OVERLAY (ALPHA path only)
    int tid = threadIdx.x;
    int base = blockIdx.x * 128;

    for (int idx = tid; idx < K * 16; idx += 256) {
        int r = idx >> 4, c4 = (idx & 15) * 4;
        float4 v = *(const float4*)&W[r * 64 + c4];
        *(uint2*)&Ws[r * 72 + c4] = cvt4(v);
    }
    if (AHALF) {
        const __half* Ah = (const __half*)Avoid;
        for (int idx = tid; idx < 128 * (K / 8); idx += 256) {
            int r = idx / (K / 8), c8 = (idx - r * (K / 8)) * 8;
            int row = base + r;
            uint4 v = (row < M) ? *(const uint4*)&Ah[row * K + c8]
                                : make_uint4(0u, 0u, 0u, 0u);
            *(uint4*)&As[r * AS + c8] = v;
        }
    } else {
        const float* Af = (const float*)Avoid;
        const int RQ = K / 4;
        for (int idx = tid; idx < 128 * RQ; idx += 256) {
            int r = idx / RQ, c4 = (idx - r * RQ) * 4;
            int row = base + r;
            float4 v = (row < M) ? *(const float4*)&Af[row * K + c4]
                                 : make_float4(0.f, 0.f, 0.f, 0.f);
            *(uint2*)&As[r * AS + c4] = cvt4(v);
        }
    }
    __syncthreads();

    int w = tid >> 5;
    wmma::fragment<wmma::matrix_a, 16, 16, 16, __half, wmma::row_major> fa;
    wmma::fragment<wmma::matrix_b, 16, 16, 16, __half, wmma::row_major> fb;
    wmma::fragment<wmma::accumulator, 16, 16, 16, float> fc[4];
#pragma unroll
    for (int j = 0; j < 4; j++) wmma::fill_fragment(fc[j], 0.f);
#pragma unroll
    for (int kk = 0; kk < K / 16; kk++) {
        wmma::load_matrix_sync(fa, As + w * 16 * AS + kk * 16, AS);
#pragma unroll
        for (int j = 0; j < 4; j++) {
            wmma::load_matrix_sync(fb, Ws + kk * 16 * 72 + j * 16, 72);
            wmma::mma_sync(fc[j], fa, fb, fc[j]);
        }
    }

    if (!ALPHA) {
        // direct half store to global (C padded past M; fp32->fp16 elementwise frag convert)
        wmma::fragment<wmma::accumulator, 16, 16, 16, __half> hc;
#pragma unroll
        for (int j = 0; j < 4; j++) {
#pragma unroll
            for (int i = 0; i < hc.num_elements; i++)
                hc.x[i] = __float2half(fc[j].x[i]);
            wmma::store_matrix_sync(C + (size_t)(base + w * 16) * 64 + j * 16,
                                    hc, 64, wmma::mem_row_major);
        }
        return;
    }

    __syncthreads();                            // all reads of As/Ws complete before overlay
#pragma unroll
    for (int j = 0; j < 4; j++)
        wmma::store_matrix_sync(Os + w * 16 * 68 + j * 16, fc[j], 68, wmma::mem_row_major);
    __syncthreads();

    // epilogue: thread t -> row t>>1, 32-col half (t&1)
    int r = tid >> 1, ch = (tid & 1) * 32;
    int row = base + r;
    float f[32];
#pragma unroll
    for (int i = 0; i < 8; i++) {
        float4 v = *(float4*)&Os[r * 68 + ch + i * 4];
        f[i * 4] = v.x; f[i * 4 + 1] = v.y; f[i * 4 + 2] = v.z; f[i * 4 + 3] = v.w;
    }
    if (row < M) {
        __half2 hh[16];
#pragma unroll
        for (int i = 0; i < 16; i++)
            hh[i] = __float22half2_rn(make_float2(f[2 * i], f[2 * i + 1]));
#pragma unroll
        for (int i = 0; i < 4; i++)
            *(uint4*)&C[row * 64 + ch + i * 8] = ((uint4*)hh)[i];
    }
    {
        float sp = 0.f, dp = 0.f;
#pragma unroll
        for (int i = 0; i < 32; i++) {
            sp = fmaf(f[i], avs[ch + i], sp);
            dp = fmaf(f[i], avd[ch + i], dp);
        }
        sp += __shfl_xor_sync(0xffffffffu, sp, 1);
        dp += __shfl_xor_sync(0xffffffffu, dp, 1);
        if ((tid & 1) == 0 && row < M) { as_out[row] = sp; ad_out[row] = dp; }
    }
}

// ======== gather helpers: lane q in quarter holds halves 8q..8q+7 ========
__device__ __forceinline__ void hacc8(const uint4* __restrict__ hp, int s, int q, float m,
                                      float acc[8]) {
    uint4 rv = hp[(unsigned)s * 8 + q];
    float2 f0 = __half22float2(*(__half2*)&rv.x);
    float2 f1 = __half22float2(*(__half2*)&rv.y);
    float2 f2 = __half22float2(*(__half2*)&rv.z);
    float2 f3 = __half22float2(*(__half2*)&rv.w);
    acc[0] = fmaf(f0.x, m, acc[0]); acc[1] = fmaf(f0.y, m, acc[1]);
    acc[2] = fmaf(f1.x, m, acc[2]); acc[3] = fmaf(f1.y, m, acc[3]);
    acc[4] = fmaf(f2.x, m, acc[4]); acc[5] = fmaf(f2.y, m, acc[5]);
    acc[6] = fmaf(f3.x, m, acc[6]); acc[7] = fmaf(f3.y, m, acc[7]);
}
// half2 chunk accumulate (HFMA2)
__device__ __forceinline__ void hacc8_h2(const uint4* __restrict__ hp, int s, int q,
                                         __half2 w, __half2 hk[4]) {
    uint4 rv = hp[(unsigned)s * 8 + q];
    __half2* rh = (__half2*)&rv;
    hk[0] = __hfma2(rh[0], w, hk[0]);
    hk[1] = __hfma2(rh[1], w, hk[1]);
    hk[2] = __hfma2(rh[2], w, hk[2]);
    hk[3] = __hfma2(rh[3], w, hk[3]);
}
__device__ __forceinline__ void flush_h2(__half2 hk[4], float acc[8]) {
#pragma unroll
    for (int j = 0; j < 4; j++) {
        float2 f = __half22float2(hk[j]);
        acc[2 * j]     += f.x;
        acc[2 * j + 1] += f.y;
    }
}

// bias + relu + fp16 pack, 16B store per group lane
__device__ __forceinline__ void agg_epilogue(float acc[8], const float* __restrict__ b,
                                             __half* __restrict__ act, int node, int lane) {
#pragma unroll
    for (int j = 0; j < 8; j++) {
        acc[j] += __shfl_xor_sync(0xffffffffu, acc[j], 8);
        acc[j] += __shfl_xor_sync(0xffffffffu, acc[j], 16);
    }
    if (lane < 8) {
        int fi = lane * 8;
        float4 b0 = *(const float4*)&b[fi];
        float4 b1 = *(const float4*)&b[fi + 4];
        __half2 hh[4];
        hh[0] = __float22half2_rn(make_float2(fmaxf(acc[0] + b0.x, 0.f), fmaxf(acc[1] + b0.y, 0.f)));
        hh[1] = __float22half2_rn(make_float2(fmaxf(acc[2] + b0.z, 0.f), fmaxf(acc[3] + b0.w, 0.f)));
        hh[2] = __float22half2_rn(make_float2(fmaxf(acc[4] + b1.x, 0.f), fmaxf(acc[5] + b1.y, 0.f)));
        hh[3] = __float22half2_rn(make_float2(fmaxf(acc[6] + b1.z, 0.f), fmaxf(acc[7] + b1.w, 0.f)));
        *(uint4*)&act[node * 64 + fi] = *(uint4*)hh;
    }
}

// ======== GCN aggregation: warp per node, quarter-warp per edge ========
__global__ void k_gcn_agg(const __half* __restrict__ h, const int* __restrict__ rp,
                          const int* __restrict__ lenv, const int* __restrict__ csr,
                          const float* __restrict__ wcsr,
                          const float* __restrict__ b, __half* __restrict__ act) {
    int node = blockIdx.x * 8 + (threadIdx.x >> 5);
    if (node >= NN) return;
    int lane = threadIdx.x & 31;
    int g = lane >> 3;          // quarter id
    int q = lane & 7;           // lane in quarter
    const uint4* hp = (const uint4*)h;
    int e = rp[node];
    int end = e + lenv[node];
    float acc[8];
#pragma unroll
    for (int j = 0; j < 8; j++) acc[j] = 0.f;
    __half2 z = __float2half2_rn(0.f);
    for (; e + 8 <= end; e += 8) {
        int eA = e + g, eB = e + 4 + g;
        int sA = csr[eA], sB = csr[eB];
        __half2 wA = __float2half2_rn(wcsr[eA]);
        __half2 wB = __float2half2_rn(wcsr[eB]);
        __half2 hk[4] = {z, z, z, z};
        hacc8_h2(hp, sA, q, wA, hk);
        hacc8_h2(hp, sB, q, wB, hk);
        flush_h2(hk, acc);
    }
    for (; e < end; e += 4) {
        int ee = e + g;
        if (ee < end) hacc8(hp, csr[ee], q, wcsr[ee], acc);
    }
    agg_epilogue(acc, b, act, node, lane);
}

__device__ __forceinline__ float lrelu(float v) { return v >= 0.f ? v : 0.2f * v; }

// ======== fused GAT aggregation: no-max softmax + exp spill + weighted gather ========
__global__ void k_gat_agg(const __half* __restrict__ h, const int* __restrict__ rp,
                          const int* __restrict__ lenv, const int* __restrict__ csr,
                          const float* __restrict__ as_, const float* __restrict__ ad_,
                          float* __restrict__ ev,
                          const float* __restrict__ b, __half* __restrict__ act) {
    int node = blockIdx.x * 8 + (threadIdx.x >> 5);
    if (node >= NN) return;
    int lane = threadIdx.x & 31;
    int g = lane >> 3;
    int q = lane & 7;
    const uint4* hp = (const uint4*)h;
    int begin = rp[node];
    int end = begin + lenv[node];
    float adv = ad_[node];

    float sum = 0.f;
    for (int e = begin + lane; e < end; e += 32) {
        float p = __expf(lrelu(as_[csr[e]] + adv));
        ev[e] = p;
        sum += p;
    }
#pragma unroll
    for (int o = 16; o; o >>= 1) sum += __shfl_xor_sync(0xffffffffu, sum, o);
    float inv = 1.f / sum;

    float acc[8];
#pragma unroll
    for (int j = 0; j < 8; j++) acc[j] = 0.f;
    __half2 z = __float2half2_rn(0.f);
    int e = begin;
    for (; e + 8 <= end; e += 8) {
        int eA = e + g, eB = e + 4 + g;
        int sA = csr[eA], sB = csr[eB];
        __half2 wA = __float2half2_rn(ev[eA] * inv);
        __half2 wB = __float2half2_rn(ev[eB] * inv);
        __half2 hk[4] = {z, z, z, z};
        hacc8_h2(hp, sA, q, wA, hk);
        hacc8_h2(hp, sB, q, wB, hk);
        flush_h2(hk, acc);
    }
    for (; e < end; e += 4) {
        int ee = e + g;
        if (ee < end) hacc8(hp, csr[ee], q, ev[ee] * inv, acc);
    }
    agg_epilogue(acc, b, act, node, lane);
}

// ======== heads + graph embedding (fp16 input; block-reduced atomics) ========
__global__ void k_heads(const __half* __restrict__ h,
                        const float* __restrict__ Wopt, const float* __restrict__ bopt,
                        const float* __restrict__ Wb1, const float* __restrict__ bb1,
                        const float* __restrict__ Wb2, const float* __restrict__ bb2,
                        float* __restrict__ out, float* __restrict__ emb,
                        int* __restrict__ ticket, int n) {
    __shared__ float sWopt[640], sbopt[10], sbb1[32], sWb2[32];
    __shared__ float hrow[8][64];
    __shared__ float semb[64];
    __shared__ int islast;
    int tid = threadIdx.x;
    for (int i = tid; i < 640; i += 256) sWopt[i] = Wopt[i];
    if (tid < 10) sbopt[tid] = bopt[tid];
    if (tid < 32) { sbb1[tid] = bb1[tid]; sWb2[tid] = Wb2[tid]; }
    if (tid < 64) semb[tid] = 0.f;
    __syncthreads();
    float bb2v = bb2[0];
    int warp = tid >> 5, lane = tid & 31;
    float wb1r[64];
#pragma unroll
    for (int k = 0; k < 64; k++) wb1r[k] = Wb1[k * 32 + lane];
    float p0 = 0.f, p1 = 0.f;
    bool opt_lane = lane < CC;
    for (int node = blockIdx.x * 8 + warp; node < n; node += gridDim.x * 8) {
        float2 hv = __half22float2(*(const __half2*)&h[node * 64 + lane * 2]);
        hrow[warp][lane * 2] = hv.x;
        hrow[warp][lane * 2 + 1] = hv.y;
        p0 += hv.x; p1 += hv.y;
        __syncwarp();
        float t = sbb1[lane];
        float acc = opt_lane ? sbopt[lane] : 0.f;
#pragma unroll
        for (int k = 0; k < 64; k++) {
            float hk = hrow[warp][k];
            t = fmaf(hk, wb1r[k], t);
            if (opt_lane) acc = fmaf(hk, sWopt[k * CC + lane], acc);
        }
        if (opt_lane) out[node * CC + lane] = acc;
        t = fmaxf(t, 0.f) * sWb2[lane];
#pragma unroll
        for (int o = 16; o; o >>= 1) t += __shfl_down_sync(0xffffffffu, t, o);
        if (lane == 0) out[NN * CC + node] = 1.f / (1.f + __expf(-(t + bb2v)));
        __syncwarp();
    }
    atomicAdd(&semb[lane * 2], p0);
    atomicAdd(&semb[lane * 2 + 1], p1);
    __syncthreads();
    if (tid < 64) atomicAdd(&emb[tid], semb[tid]);
    __threadfence();
    if (tid == 0) {
        int done = atomicAdd(ticket, 1);
        islast = (done == gridDim.x - 1);
    }
    __syncthreads();
    if (islast) {
        if (tid < 64) out[NN * CC + NN + tid] = emb[tid] * (1.0f / NN);
        if (tid == 0) *ticket = 0;
    }
}

// ======== launch ========
extern "C" void kernel_launch(void* const* d_in, const int* in_sizes, int n_in,
                              void* d_out, int out_size) {
    const float* x    = (const float*)d_in[0];
    const int*   ei   = (const int*)d_in[1];
    const int*   src  = ei;
    const int*   dst  = ei + EE;
    const float* W1   = (const float*)d_in[2];
    const float* b1   = (const float*)d_in[3];
    const float* W2   = (const float*)d_in[4];
    const float* a_s  = (const float*)d_in[5];
    const float* a_d  = (const float*)d_in[6];
    const float* b2   = (const float*)d_in[7];
    const float* W3   = (const float*)d_in[8];
    const float* b3   = (const float*)d_in[9];
    const float* Wopt = (const float*)d_in[10];
    const float* bopt = (const float*)d_in[11];
    const float* Wb1  = (const float*)d_in[12];
    const float* bb1  = (const float*)d_in[13];
    const float* Wb2  = (const float*)d_in[14];
    const float* bb2  = (const float*)d_in[15];
    float* out = (float*)d_out;

    __half *pLin, *pAct;
    float *pDinv, *pAs, *pAd, *pEmb, *pWcsr, *pEv;
    int *pDeg, *pRp, *pLen, *pCur, *pCsr, *pCtr;
    cudaGetSymbolAddress((void**)&pLin,  g_lin);
    cudaGetSymbolAddress((void**)&pAct,  g_act);
    cudaGetSymbolAddress((void**)&pDeg,  g_deg);
    cudaGetSymbolAddress((void**)&pRp,   g_rowptr);
    cudaGetSymbolAddress((void**)&pLen,  g_len);
    cudaGetSymbolAddress((void**)&pCur,  g_cursor);
    cudaGetSymbolAddress((void**)&pCsr,  g_csr);
    cudaGetSymbolAddress((void**)&pWcsr, g_wcsr);
    cudaGetSymbolAddress((void**)&pEv,   g_ev);
    cudaGetSymbolAddress((void**)&pDinv, g_dinv);
    cudaGetSymbolAddress((void**)&pAs,   g_as);
    cudaGetSymbolAddress((void**)&pAd,   g_ad);
    cudaGetSymbolAddress((void**)&pEmb,  g_emb);
    cudaGetSymbolAddress((void**)&pCtr,  g_ctr);

    const int TB = 256;
    const int nBlkA = (NN + 7) / 8;                // warp per node
    const int nBlkG = (NN + 127) / 128;
    const int smemAlpha = 128 * 68 * 4;            // 34816 (Os overlay, ALPHA path)
    const int smemD32 = 128 * 40 * 2 + 32 * 72 * 2;   // 14848 (direct, K=32)
    const int smemD64 = 128 * 72 * 2 + 64 * 72 * 2;   // 27648 (direct, K=64)

    static cudaStream_t s1 = nullptr;
    static cudaEvent_t ev0 = nullptr, ev1 = nullptr;
    static int attr_done = 0;
    if (!attr_done) {
        cudaFuncSetAttribute((const void*)k_gemm_t<64, true, true>,
                             cudaFuncAttributeMaxDynamicSharedMemorySize, smemAlpha);
        cudaFuncSetAttribute((const void*)k_gemm_t<64, false, true>,
                             cudaFuncAttributeMaxDynamicSharedMemorySize, smemD64);
        cudaFuncSetAttribute((const void*)k_gemm_t<32, false, false>,
                             cudaFuncAttributeMaxDynamicSharedMemorySize, smemD32);
        cudaStreamCreateWithFlags(&s1, cudaStreamNonBlocking);
        cudaEventCreateWithFlags(&ev0, cudaEventDisableTiming);
        cudaEventCreateWithFlags(&ev1, cudaEventDisableTiming);
        attr_done = 1;
    }

    // ---- fork: CSR build on s1, overlapped with GEMM1 on stream 0 ----
    cudaEventRecord(ev0, 0);
    cudaStreamWaitEvent(s1, ev0, 0);
    k_deg_count<<<(EE + 1023) / 1024, TB, 0, s1>>>(dst, pDeg);
    k_rp<<<NB, TB, 0, s1>>>(pDeg, pRp, pCur, pLen, pDinv, pEmb, pCtr);
    k_csr_fill<<<(ET + 1023) / 1024, TB, 0, s1>>>(src, dst, pCur, pCsr, pDinv, pWcsr);
    cudaEventRecord(ev1, s1);

    // ---- GCN layer 1 ----
    k_gemm_t<32, false, false><<<nBlkG, TB, smemD32>>>(x, W1, pLin, nullptr, nullptr, nullptr, nullptr, NN);
    cudaStreamWaitEvent(0, ev1, 0);   // join: aggs need CSR + weights
    k_gcn_agg<<<nBlkA, TB>>>(pLin, pRp, pLen, pCsr, pWcsr, b1, pAct);

    // ---- GAT layer (alpha fused into GEMM epilogue) ----
    k_gemm_t<64, true, true><<<nBlkG, TB, smemAlpha>>>(pAct, W2, pLin, a_s, a_d, pAs, pAd, NN);
    k_gat_agg<<<nBlkA, TB>>>(pLin, pRp, pLen, pCsr, pAs, pAd, pEv, b2, pAct);

    // ---- GCN layer 3 ----
    k_gemm_t<64, false, true><<<nBlkG, TB, smemD64>>>(pAct, W3, pLin, nullptr, nullptr, nullptr, nullptr, NN);
    k_gcn_agg<<<nBlkA, TB>>>(pLin, pRp, pLen, pCsr, pWcsr, b3, pAct);

    // ---- heads + embedding (finish fused via last-block ticket) ----
    k_heads<<<1184, TB>>>(pAct, Wopt, bopt, Wb1, bb1, Wb2, bb2, out, pEmb, pCtr + 2, NN);
}